// round 1
// baseline (speedup 1.0000x reference)
#include <cuda_runtime.h>

#define N_CONST 4096
#define A_TOT   256
#define D_IN    39
#define H       50
#define S_TOT   8
#define ROWP    52          // padded row length in floats (16B aligned rows)
#define HP      25          // 50/2 packed pairs
#define BLK     128         // threads per block (one n per thread)

typedef unsigned long long u64;

__device__ __forceinline__ u64 packpair(float lo, float hi) {
    u64 r; asm("mov.b64 %0, {%1, %2};" : "=l"(r) : "f"(lo), "f"(hi)); return r;
}
__device__ __forceinline__ u64 pack2(float v) {
    u64 r; asm("mov.b64 %0, {%1, %1};" : "=l"(r) : "f"(v)); return r;
}
__device__ __forceinline__ void unpack2(u64 v, float& lo, float& hi) {
    asm("mov.b64 {%0, %1}, %2;" : "=f"(lo), "=f"(hi) : "l"(v));
}
__device__ __forceinline__ u64 fma2(u64 a, u64 b, u64 c) {
    u64 d; asm("fma.rn.f32x2 %0, %1, %2, %3;" : "=l"(d) : "l"(a), "l"(b), "l"(c));
    return d;
}
__device__ __forceinline__ float silu_f(float v) {
    return __fdividef(v, 1.0f + __expf(-v));
}

__global__ __launch_bounds__(BLK, 4)
void atomic_mlp_kernel(const float* __restrict__ desc,
                       const int*   __restrict__ numbers,
                       const float* __restrict__ W1, const float* __restrict__ b1,
                       const float* __restrict__ W2, const float* __restrict__ b2,
                       const float* __restrict__ W3, const float* __restrict__ b3,
                       float* __restrict__ out, int N)
{
    // weights of this block's species, rows padded to ROWP for LDS.128
    __shared__ __align__(16) float sW1[D_IN * ROWP];   //  8112 B
    __shared__ __align__(16) float sW2[H * ROWP];      // 10400 B
    __shared__ __align__(16) float sB1[ROWP];
    __shared__ __align__(16) float sB2[ROWP];
    __shared__ __align__(16) float sW3[ROWP];
    __shared__ float sB3v;
    // staged descriptor tile: BLK rows x 39 (word-stride 39 is odd => conflict-free)
    __shared__ __align__(16) float sx[BLK * D_IN];     // 19968 B

    const int a = blockIdx.x;
    const int t = threadIdx.x;
    const int s = numbers[a];

    // ---- stage weights (padded with zeros; pads multiply into dead slots) ----
    for (int i = t; i < D_IN * ROWP; i += BLK) {
        int d = i / ROWP, j = i - d * ROWP;
        sW1[i] = (j < H) ? W1[(s * D_IN + d) * H + j] : 0.0f;
    }
    for (int i = t; i < H * ROWP; i += BLK) {
        int d = i / ROWP, j = i - d * ROWP;
        sW2[i] = (j < H) ? W2[(s * H + d) * H + j] : 0.0f;
    }
    if (t < ROWP) {
        sB1[t] = (t < H) ? b1[s * H + t] : 0.0f;
        sB2[t] = (t < H) ? b2[s * H + t] : 0.0f;
        sW3[t] = (t < H) ? W3[s * H + t] : 0.0f;
    }
    if (t == 0) sB3v = b3[s];

    // ---- stage this block's desc tile, coalesced ----
    {
        const size_t rowstride = (size_t)A_TOT * D_IN;
        const size_t base = (size_t)blockIdx.y * BLK * rowstride + (size_t)a * D_IN;
        for (int i = t; i < BLK * D_IN; i += BLK) {
            int r = i / D_IN, c = i - r * D_IN;
            sx[i] = desc[base + (size_t)r * rowstride + c];
        }
    }
    __syncthreads();

    const int n = blockIdx.y * BLK + t;

    // ================= layer 1: h1 = silu(x @ W1 + b1) =================
    u64 h1[HP];
    {
        const u64* bp = reinterpret_cast<const u64*>(sB1);
        #pragma unroll
        for (int p = 0; p < HP; p++) h1[p] = bp[p];
    }
    #pragma unroll
    for (int d = 0; d < D_IN; d++) {
        u64 xx = pack2(sx[t * D_IN + d]);
        const ulonglong2* wv = reinterpret_cast<const ulonglong2*>(&sW1[d * ROWP]);
        #pragma unroll
        for (int p = 0; p < 12; p++) {
            ulonglong2 w = wv[p];
            h1[2 * p]     = fma2(xx, w.x, h1[2 * p]);
            h1[2 * p + 1] = fma2(xx, w.y, h1[2 * p + 1]);
        }
        h1[24] = fma2(xx, *reinterpret_cast<const u64*>(&sW1[d * ROWP + 48]), h1[24]);
    }
    float hf[H];
    #pragma unroll
    for (int p = 0; p < HP; p++) {
        float lo, hi; unpack2(h1[p], lo, hi);
        hf[2 * p]     = silu_f(lo);
        hf[2 * p + 1] = silu_f(hi);
    }

    // ================= layer 2: h2 = silu(h1 @ W2 + b2) =================
    u64 h2[HP];
    {
        const u64* bp = reinterpret_cast<const u64*>(sB2);
        #pragma unroll
        for (int p = 0; p < HP; p++) h2[p] = bp[p];
    }
    #pragma unroll
    for (int d = 0; d < H; d++) {
        u64 xx = pack2(hf[d]);
        const ulonglong2* wv = reinterpret_cast<const ulonglong2*>(&sW2[d * ROWP]);
        #pragma unroll
        for (int p = 0; p < 12; p++) {
            ulonglong2 w = wv[p];
            h2[2 * p]     = fma2(xx, w.x, h2[2 * p]);
            h2[2 * p + 1] = fma2(xx, w.y, h2[2 * p + 1]);
        }
        h2[24] = fma2(xx, *reinterpret_cast<const u64*>(&sW2[d * ROWP + 48]), h2[24]);
    }

    // ================= layer 3: out = silu(h2) @ W3 + b3 =================
    u64 acc = 0ULL;
    {
        const u64* w3p = reinterpret_cast<const u64*>(sW3);
        #pragma unroll
        for (int p = 0; p < HP; p++) {
            float lo, hi; unpack2(h2[p], lo, hi);
            u64 sp = packpair(silu_f(lo), silu_f(hi));
            acc = fma2(sp, w3p[p], acc);
        }
    }
    float alo, ahi; unpack2(acc, alo, ahi);
    out[(size_t)n * A_TOT + a] = alo + ahi + sB3v;
}

extern "C" void kernel_launch(void* const* d_in, const int* in_sizes, int n_in,
                              void* d_out, int out_size)
{
    const float* desc    = (const float*)d_in[0];
    const int*   numbers = (const int*)  d_in[1];
    const float* W1      = (const float*)d_in[2];
    const float* b1      = (const float*)d_in[3];
    const float* W2      = (const float*)d_in[4];
    const float* b2      = (const float*)d_in[5];
    const float* W3      = (const float*)d_in[6];
    const float* b3      = (const float*)d_in[7];
    float* out = (float*)d_out;

    const int N = in_sizes[0] / (A_TOT * D_IN);   // 4096
    dim3 grid(A_TOT, N / BLK);
    atomic_mlp_kernel<<<grid, BLK>>>(desc, numbers, W1, b1, W2, b2, W3, b3, out, N);
}